// round 5
// baseline (speedup 1.0000x reference)
#include <cuda_runtime.h>

#define NN      50000      // nodes
#define NIN     128        // node in-dim
#define NOUT    64         // node out-dim
#define EIN     32         // edge feat dim
#define NE      400000     // undirected edges
#define ND      (2*NE)     // directed edges
#define ALPHA_L 0.2f
#define EPSV    1e-12f
#define NPART   256
#define FULLM   0xffffffffu

// ---------------- scratch (device globals) -------------------------------------
__device__ __align__(16) float g_hv[NN * NOUT];   // h_v
__device__ float  g_s1[NN];
__device__ float  g_s2[NN];
__device__ float  g_hn[NN];
__device__ float  g_lr[ND];            // leaky logits, [u]=dir x->y, [u+NE]=dir y->x
__device__ int    g_cnt[NN];           // out-degree histogram (directed)
__device__ int    g_off[NN + 1];       // CSR offsets
__device__ int    g_cur[NN];           // scatter cursors
__device__ __align__(8) int2 g_pair[ND];  // CSR entries: {dst, lr-as-int}
__device__ double g_psum[NPART];
__device__ double g_psq[NPART];

// ---------------- k1: zero prologue + GEMM + scalars + out[:,0:64] ---------------
__global__ void k1_gemm(const float* __restrict__ nf,
                        const float* __restrict__ W,
                        const float* __restrict__ b,
                        const float* __restrict__ an,
                        float* __restrict__ out) {
    extern __shared__ float sm[];
    float* Ws = sm;            // 8192 floats (32 KB)
    float* Ns = sm + 8192;     // 16384 floats (64 KB)
    int tid = threadIdx.x;
    int base = blockIdx.x * 128;
    int gid = blockIdx.x * 256 + tid;

    // prologue: zero histogram + variance partials (grid = 100096 >= NN)
    if (gid < NN) g_cnt[gid] = 0;
    if (gid < NPART) { g_psum[gid] = 0.0; g_psq[gid] = 0.0; }

    for (int i = tid; i < (NIN * NOUT) / 4; i += 256)
        ((float4*)Ws)[i] = ((const float4*)W)[i];
    for (int i = tid; i < (128 * NIN) / 4; i += 256) {
        int node = base + (i >> 5);
        float4 v = make_float4(0.f, 0.f, 0.f, 0.f);
        if (node < NN) v = ((const float4*)nf)[(long)node * 32 + (i & 31)];
        ((float4*)Ns)[i] = v;
    }
    __syncthreads();

    int cg = tid & 15;
    int ng = tid >> 4;
    const float* nb = &Ns[ng * 8 * NIN];

    float4 acc[8];
#pragma unroll
    for (int n = 0; n < 8; n++) acc[n] = make_float4(0.f, 0.f, 0.f, 0.f);

#pragma unroll 4
    for (int k = 0; k < NIN; k++) {
        float4 wv = *(const float4*)&Ws[k * NOUT + cg * 4];
#pragma unroll
        for (int n = 0; n < 8; n++) {
            float av = nb[n * NIN + k];
            acc[n].x += av * wv.x;
            acc[n].y += av * wv.y;
            acc[n].z += av * wv.z;
            acc[n].w += av * wv.w;
        }
    }

    float4 bv = *(const float4*)&b[cg * 4];
    __syncthreads();                         // done reading Ns; reuse as hvt
    float* hvt = Ns;
#pragma unroll
    for (int n = 0; n < 8; n++) {
        acc[n].x += bv.x; acc[n].y += bv.y; acc[n].z += bv.z; acc[n].w += bv.w;
        int node = base + ng * 8 + n;
        if (node < NN) {
            ((float4*)g_hv)[(long)node * 16 + cg] = acc[n];
            ((float4*)out) [(long)node * 32 + cg] = acc[n];   // out cols 0..63
        }
        *(float4*)&hvt[(ng * 8 + n) * NOUT + cg * 4] = acc[n];
    }
    __syncthreads();

    // per-node scalars: 8 warps x 16 nodes each
    int wp = tid >> 5, l = tid & 31;
    float a1x = __ldg(&an[2*l]),      a1y = __ldg(&an[2*l+1]);
    float a2x = __ldg(&an[64 + 2*l]), a2y = __ldg(&an[64 + 2*l+1]);
#pragma unroll
    for (int i = 0; i < 16; i++) {
        int n = wp * 16 + i;
        int node = base + n;
        float2 h = ((const float2*)hvt)[n * 32 + l];
        float s1 = h.x * a1x + h.y * a1y;
        float s2 = h.x * a2x + h.y * a2y;
        float sq = h.x * h.x + h.y * h.y;
#pragma unroll
        for (int o = 16; o; o >>= 1) {
            s1 += __shfl_down_sync(FULLM, s1, o);
            s2 += __shfl_down_sync(FULLM, s2, o);
            sq += __shfl_down_sync(FULLM, sq, o);
        }
        if (l == 0 && node < NN) {
            g_s1[node] = s1; g_s2[node] = s2; g_hn[node] = sqrtf(sq);
        }
    }
}

// ---------------- kE: edge dot + leaky logits (both dirs) + degree hist ----------
// Warp = 8 undirected edges. Coalesced 1KB edge-feature read; lanes 0-15 then
// handle 8 edges x 2 directions in parallel.
__global__ void kE_edge(const float* __restrict__ ef,
                        const float* __restrict__ an,
                        const int* __restrict__ p) {
    int w = (blockIdx.x * blockDim.x + threadIdx.x) >> 5;   // 0..49999
    int l = threadIdx.x & 31;
    int row0 = w * 8;                                       // NE % 8 == 0
    const float4* ef4 = (const float4*)ef;
    float4 v0 = __ldg(&ef4[(long)row0 * 8 + l]);            // rows row0+0..3
    float4 v1 = __ldg(&ef4[(long)row0 * 8 + 32 + l]);       // rows row0+4..7
    const float* a3 = an + 2 * NOUT;
    int q = l & 7;
    float ax = __ldg(&a3[4*q]),   ay = __ldg(&a3[4*q+1]);
    float az = __ldg(&a3[4*q+2]), aw = __ldg(&a3[4*q+3]);
    float s0 = v0.x*ax + v0.y*ay + v0.z*az + v0.w*aw;
    float s1 = v1.x*ax + v1.y*ay + v1.z*az + v1.w*aw;
#pragma unroll
    for (int o = 4; o; o >>= 1) {
        s0 += __shfl_xor_sync(FULLM, s0, o);
        s1 += __shfl_xor_sync(FULLM, s1, o);
    }
    // lanes {0,8,16,24} hold t for rows row0+{0..3} (s0) and row0+{4..7} (s1)
    int srcl = (l & 3) << 3;
    float ta = __shfl_sync(FULLM, s0, srcl);
    float tb = __shfl_sync(FULLM, s1, srcl);
    float tu = ((l & 7) < 4) ? ta : tb;

    if (l < 16) {
        int e = l & 7, dir = l >> 3;       // dir0: src=x,dst=y ; dir1: src=y,dst=x
        int u = row0 + e;
        int2 xy = __ldg(&((const int2*)p)[u]);
        int src = dir ? xy.y : xy.x;
        int dst = dir ? xy.x : xy.y;
        float lg = __ldg(&g_s1[src]) + __ldg(&g_s2[dst]) + tu;
        float lr = (lg > 0.f) ? lg : ALPHA_L * lg;
        g_lr[u + dir * NE] = lr;
        atomicAdd(&g_cnt[src], 1);
    }
}

// ---------------- kB: exclusive scan -> offsets + cursors ------------------------
__global__ void kB_scan() {
    __shared__ int sums[1024];
    const int CH = (NN + 1023) / 1024;   // 49
    int t = threadIdx.x;
    int s = 0;
    for (int k = 0; k < CH; k++) {
        int idx = t * CH + k;
        if (idx < NN) s += g_cnt[idx];
    }
    sums[t] = s;
    __syncthreads();
    for (int o = 1; o < 1024; o <<= 1) {
        int v = (t >= o) ? sums[t - o] : 0;
        __syncthreads();
        sums[t] += v;
        __syncthreads();
    }
    int pre = (t > 0) ? sums[t - 1] : 0;
    for (int k = 0; k < CH; k++) {
        int idx = t * CH + k;
        if (idx < NN) {
            int c = g_cnt[idx];
            g_off[idx] = pre;
            g_cur[idx] = pre;
            pre += c;
        }
    }
    if (t == 1023) g_off[NN] = pre;
}

// ---------------- kC: scatter CSR entries {dst, lr} ------------------------------
__global__ void kC_scatter(const int* __restrict__ p) {
    int u = blockIdx.x * blockDim.x + threadIdx.x;
    if (u >= NE) return;
    int2 xy = __ldg(&((const int2*)p)[u]);
    float lr1 = __ldg(&g_lr[u]);        // src=x, dst=y
    float lr2 = __ldg(&g_lr[u + NE]);   // src=y, dst=x
    int p1 = atomicAdd(&g_cur[xy.x], 1);
    g_pair[p1] = make_int2(xy.y, __float_as_int(lr1));
    int p2 = atomicAdd(&g_cur[xy.y], 1);
    g_pair[p2] = make_int2(xy.x, __float_as_int(lr2));
}

// ---------------- kD: per-node softmax-sum + gather + normalize + output ---------
// Warp per node. Pass 1: attlog from CSR. Pass 2: 4 edge-groups x 8 lanes, each
// lane 2 coalesced LDG.128 per edge, register accumulators, xor-reduce at end.
__global__ void kD_node(float* __restrict__ out, const float* __restrict__ scale) {
    __shared__ float ssum[8], ssq[8];
    int wp = threadIdx.x >> 5, l = threadIdx.x & 31;
    int v = blockIdx.x * 8 + wp;
    float vs = 0.f, vq = 0.f;
    if (v < NN) {
        int start = __ldg(&g_off[v]);
        int deg   = __ldg(&g_off[v + 1]) - start;

        // pass 1: attsum
        float esum = 0.f;
        for (int i = l; i < deg; i += 32)
            esum += __expf(__int_as_float(__ldg(&g_pair[start + i]).y));
#pragma unroll
        for (int o = 16; o; o >>= 1) esum += __shfl_xor_sync(FULLM, esum, o);
        float attlog = __logf(esum);

        // pass 2: gather-accumulate
        int eg = l >> 3, q = l & 7;
        float4 m0 = make_float4(0.f, 0.f, 0.f, 0.f);
        float4 m1 = make_float4(0.f, 0.f, 0.f, 0.f);
        for (int bse = 0; bse < deg; bse += 4) {
            int i = bse + eg;
            if (i < deg) {
                int2 pr = __ldg(&g_pair[start + i]);
                float an = __int_as_float(pr.y) - attlog;
                if (q == 0) { vs += an; vq += an * an; }
                const float4* hp = &((const float4*)g_hv)[(long)pr.x * 16];
                float4 h0 = __ldg(&hp[q]);       // cols 4q..4q+3
                float4 h1 = __ldg(&hp[8 + q]);   // cols 32+4q..32+4q+3
                m0.x += h0.x * an; m0.y += h0.y * an; m0.z += h0.z * an; m0.w += h0.w * an;
                m1.x += h1.x * an; m1.y += h1.y * an; m1.z += h1.z * an; m1.w += h1.w * an;
            }
        }
        // reduce across the 4 edge-groups (xor 8, 16)
#pragma unroll
        for (int o = 8; o <= 16; o <<= 1) {
            m0.x += __shfl_xor_sync(FULLM, m0.x, o);
            m0.y += __shfl_xor_sync(FULLM, m0.y, o);
            m0.z += __shfl_xor_sync(FULLM, m0.z, o);
            m0.w += __shfl_xor_sync(FULLM, m0.w, o);
            m1.x += __shfl_xor_sync(FULLM, m1.x, o);
            m1.y += __shfl_xor_sync(FULLM, m1.y, o);
            m1.z += __shfl_xor_sync(FULLM, m1.z, o);
            m1.w += __shfl_xor_sync(FULLM, m1.w, o);
        }
        float sq = m0.x*m0.x + m0.y*m0.y + m0.z*m0.z + m0.w*m0.w
                 + m1.x*m1.x + m1.y*m1.y + m1.z*m1.z + m1.w*m1.w;
#pragma unroll
        for (int o = 4; o; o >>= 1) sq += __shfl_xor_sync(FULLM, sq, o);
        float r = __ldg(&g_hn[v]) * __ldg(scale) / fmaxf(sqrtf(sq), EPSV);
        if (l < 8) {
            float4* orow = (float4*)(out + (long)v * 128);
            orow[16 + q] = make_float4(m0.x*r, m0.y*r, m0.z*r, m0.w*r);
            orow[24 + q] = make_float4(m1.x*r, m1.y*r, m1.z*r, m1.w*r);
        }
    }
    // variance partials: contributions live on lanes 0,8,16,24
    vs += __shfl_xor_sync(FULLM, vs, 8);  vs += __shfl_xor_sync(FULLM, vs, 16);
    vq += __shfl_xor_sync(FULLM, vq, 8);  vq += __shfl_xor_sync(FULLM, vq, 16);
    if (l == 0) { ssum[wp] = vs; ssq[wp] = vq; }
    __syncthreads();
    if (threadIdx.x == 0) {
        float bs = 0.f, bq = 0.f;
#pragma unroll
        for (int i = 0; i < 8; i++) { bs += ssum[i]; bq += ssq[i]; }
        atomicAdd(&g_psum[blockIdx.x & (NPART - 1)], (double)bs);
        atomicAdd(&g_psq [blockIdx.x & (NPART - 1)], (double)bq);
    }
}

// ---------------- k5: variance -> out[NN*128] -------------------------------------
__global__ void k5_var(float* __restrict__ out) {
    __shared__ double s[NPART], q[NPART];
    int t = threadIdx.x;
    s[t] = g_psum[t]; q[t] = g_psq[t];
    __syncthreads();
    for (int o = NPART / 2; o; o >>= 1) {
        if (t < o) { s[t] += s[t + o]; q[t] += q[t + o]; }
        __syncthreads();
    }
    if (t == 0) {
        double E = (double)ND;
        double var = (q[0] - s[0] * s[0] / E) / (E - 1.0);
        out[(long)NN * 128] = (float)var;
    }
}

// ---------------- launch --------------------------------------------------------------
extern "C" void kernel_launch(void* const* d_in, const int* in_sizes, int n_in,
                              void* d_out, int out_size) {
    const float* nf    = (const float*)d_in[0];
    const float* ef    = (const float*)d_in[1];
    const int*   edges = (const int*)  d_in[2];
    const float* W     = (const float*)d_in[3];
    const float* b     = (const float*)d_in[4];
    const float* an    = (const float*)d_in[5];
    const float* scale = (const float*)d_in[6];
    float* out = (float*)d_out;

    const int k1_smem = (8192 + 16384) * 4;  // 96 KB
    cudaFuncSetAttribute(k1_gemm, cudaFuncAttributeMaxDynamicSharedMemorySize, k1_smem);

    k1_gemm   <<<(NN + 127)/128, 256, k1_smem>>>(nf, W, b, an, out);
    kE_edge   <<<NE/8/8, 256>>>(ef, an, edges);      // 6250 blocks, warp = 8 edges
    kB_scan   <<<1, 1024>>>();
    kC_scatter<<<(NE + 255)/256, 256>>>(edges);
    kD_node   <<<(NN + 7)/8, 256>>>(out, scale);     // 6250 blocks, warp = 1 node
    k5_var    <<<1, NPART>>>(out);
}

// round 6
// speedup vs baseline: 1.6305x; 1.6305x over previous
#include <cuda_runtime.h>

#define NN      50000      // nodes
#define NIN     128        // node in-dim
#define NOUT    64         // node out-dim
#define EIN     32         // edge feat dim
#define NE      400000     // undirected edges
#define ND      (2*NE)     // directed edges
#define ALPHA_L 0.2f
#define EPSV    1e-12f
#define NPART   256
#define FULLM   0xffffffffu

// ---------------- scratch (device globals) -------------------------------------
__device__ __align__(16) float g_hv[NN * NOUT];   // h_v
__device__ __align__(16) float g_msg[NN * NOUT];  // segment sum by src
__device__ float  g_s1[NN];
__device__ float  g_s2[NN];
__device__ float  g_hn[NN];
__device__ float  g_attsum[NN];
__device__ float  g_lr[ND];
__device__ double g_psum[NPART];
__device__ double g_psq[NPART];

// vector RED: 4 floats in one L2 atomic op (sm_90+)
__device__ __forceinline__ void red_v4(float* addr, float4 v) {
    asm volatile("red.global.add.v4.f32 [%0], {%1,%2,%3,%4};"
                 :: "l"(addr), "f"(v.x), "f"(v.y), "f"(v.z), "f"(v.w) : "memory");
}

// ---------------- k1: zero prologue + GEMM + scalars + out[:,0:64] ---------------
// 256 threads, 128 nodes/block, thread tile 8 nodes x 4 cols.
__global__ void k1_gemm(const float* __restrict__ nf,
                        const float* __restrict__ W,
                        const float* __restrict__ b,
                        const float* __restrict__ an,
                        float* __restrict__ out) {
    extern __shared__ float sm[];
    float* Ws = sm;            // 8192 floats (32 KB)
    float* Ns = sm + 8192;     // 16384 floats (64 KB)
    int tid = threadIdx.x;
    int base = blockIdx.x * 128;
    int gid = blockIdx.x * 256 + tid;

    // prologue: zero attsum + variance partials (grid = 100096 >= NN)
    if (gid < NN) g_attsum[gid] = 0.f;
    if (gid < NPART) { g_psum[gid] = 0.0; g_psq[gid] = 0.0; }

    for (int i = tid; i < (NIN * NOUT) / 4; i += 256)
        ((float4*)Ws)[i] = ((const float4*)W)[i];
    for (int i = tid; i < (128 * NIN) / 4; i += 256) {
        int node = base + (i >> 5);
        float4 v = make_float4(0.f, 0.f, 0.f, 0.f);
        if (node < NN) v = ((const float4*)nf)[(long)node * 32 + (i & 31)];
        ((float4*)Ns)[i] = v;
    }
    __syncthreads();

    int cg = tid & 15;
    int ng = tid >> 4;
    const float* nb = &Ns[ng * 8 * NIN];

    float4 acc[8];
#pragma unroll
    for (int n = 0; n < 8; n++) acc[n] = make_float4(0.f, 0.f, 0.f, 0.f);

#pragma unroll 4
    for (int k = 0; k < NIN; k++) {
        float4 wv = *(const float4*)&Ws[k * NOUT + cg * 4];
#pragma unroll
        for (int n = 0; n < 8; n++) {
            float av = nb[n * NIN + k];
            acc[n].x += av * wv.x;
            acc[n].y += av * wv.y;
            acc[n].z += av * wv.z;
            acc[n].w += av * wv.w;
        }
    }

    float4 bv = *(const float4*)&b[cg * 4];
    __syncthreads();                         // done reading Ns; reuse as hvt
    float* hvt = Ns;
#pragma unroll
    for (int n = 0; n < 8; n++) {
        acc[n].x += bv.x; acc[n].y += bv.y; acc[n].z += bv.z; acc[n].w += bv.w;
        int node = base + ng * 8 + n;
        if (node < NN) {
            ((float4*)g_hv)[(long)node * 16 + cg] = acc[n];
            ((float4*)out) [(long)node * 32 + cg] = acc[n];   // out cols 0..63
        }
        *(float4*)&hvt[(ng * 8 + n) * NOUT + cg * 4] = acc[n];
    }
    __syncthreads();

    // per-node scalars: 8 warps x 16 nodes each
    int wp = tid >> 5, l = tid & 31;
    float a1x = __ldg(&an[2*l]),      a1y = __ldg(&an[2*l+1]);
    float a2x = __ldg(&an[64 + 2*l]), a2y = __ldg(&an[64 + 2*l+1]);
#pragma unroll
    for (int i = 0; i < 16; i++) {
        int n = wp * 16 + i;
        int node = base + n;
        float2 h = ((const float2*)hvt)[n * 32 + l];
        float s1 = h.x * a1x + h.y * a1y;
        float s2 = h.x * a2x + h.y * a2y;
        float sq = h.x * h.x + h.y * h.y;
#pragma unroll
        for (int o = 16; o; o >>= 1) {
            s1 += __shfl_down_sync(FULLM, s1, o);
            s2 += __shfl_down_sync(FULLM, s2, o);
            sq += __shfl_down_sync(FULLM, sq, o);
        }
        if (l == 0 && node < NN) {
            g_s1[node] = s1; g_s2[node] = s2; g_hn[node] = sqrtf(sq);
        }
    }
}

// ---------------- kE: edge dot + attention (both dirs) + zero g_msg --------------
// Warp = 16 undirected edges (2KB coalesced ef read, 4 float4/lane). After the
// dot-product reduction, all 32 lanes own one (edge, direction) pair.
__global__ void kE_edge(const float* __restrict__ ef,
                        const float* __restrict__ an,
                        const int* __restrict__ p) {
    long gid = (long)blockIdx.x * blockDim.x + threadIdx.x;
    // zero msg: 800000 threads cover 800000 float4s exactly
    ((float4*)g_msg)[gid] = make_float4(0.f, 0.f, 0.f, 0.f);

    int w = (int)(gid >> 5);
    int l = threadIdx.x & 31;
    int row0 = w * 16;                       // NE % 16 == 0, grid exact
    const float4* ef4 = (const float4*)ef + (long)row0 * 8;
    float4 v0 = __ldg(&ef4[l]);
    float4 v1 = __ldg(&ef4[32 + l]);
    float4 v2 = __ldg(&ef4[64 + l]);
    float4 v3 = __ldg(&ef4[96 + l]);
    const float* a3 = an + 2 * NOUT;
    int q = l & 7;
    float ax = __ldg(&a3[4*q]),   ay = __ldg(&a3[4*q+1]);
    float az = __ldg(&a3[4*q+2]), aw = __ldg(&a3[4*q+3]);
    // chunk c, lane l -> local row 4c + (l>>3), quarter q
    float s0 = v0.x*ax + v0.y*ay + v0.z*az + v0.w*aw;
    float s1 = v1.x*ax + v1.y*ay + v1.z*az + v1.w*aw;
    float s2 = v2.x*ax + v2.y*ay + v2.z*az + v2.w*aw;
    float s3 = v3.x*ax + v3.y*ay + v3.z*az + v3.w*aw;
#pragma unroll
    for (int o = 4; o; o >>= 1) {
        s0 += __shfl_xor_sync(FULLM, s0, o);
        s1 += __shfl_xor_sync(FULLM, s1, o);
        s2 += __shfl_xor_sync(FULLM, s2, o);
        s3 += __shfl_xor_sync(FULLM, s3, o);
    }
    // s_c on lane-group g (= l>>3) holds t[4c + g].
    // lane l handles edge e = l&15 (dir = l>>4): t[e] = s_{e>>2} from lane (e&3)*8.
    int e = l & 15, dir = l >> 4;
    int srcl = (e & 3) << 3;
    float t0 = __shfl_sync(FULLM, s0, srcl);
    float t1 = __shfl_sync(FULLM, s1, srcl);
    float t2 = __shfl_sync(FULLM, s2, srcl);
    float t3 = __shfl_sync(FULLM, s3, srcl);
    int c = e >> 2;
    float tu = (c == 0) ? t0 : (c == 1) ? t1 : (c == 2) ? t2 : t3;

    int u = row0 + e;
    int2 xy = __ldg(&((const int2*)p)[u]);
    int src = dir ? xy.y : xy.x;
    int dst = dir ? xy.x : xy.y;
    float lg = __ldg(&g_s1[src]) + __ldg(&g_s2[dst]) + tu;
    float lr = (lg > 0.f) ? lg : ALPHA_L * lg;
    g_lr[u + dir * NE] = lr;
    atomicAdd(&g_attsum[src], __expf(lr));
}

// ---------------- k4: msg scatter (vector RED, deep prefetch) + var partials -----
#define ED 8   // undirected edges per warp
__global__ void k4_scatter(const int* __restrict__ p) {
    __shared__ float ssum[8], ssq[8];
    int warp = (blockIdx.x * blockDim.x + threadIdx.x) >> 5;
    int l = threadIdx.x & 31;
    int half = l >> 4, q = l & 15;
    long base = (long)warp * ED;           // NE % ED == 0, grid exact

    int2  xy[ED];
    float l1[ED], l2[ED];
#pragma unroll
    for (int e = 0; e < ED; e++) {
        long u = base + e;
        xy[e] = __ldg(&((const int2*)p)[u]);
        l1[e] = __ldg(&g_lr[u]);
        l2[e] = __ldg(&g_lr[u + NE]);
    }
    float a1[ED], a2[ED];
    float4 h[ED];
#pragma unroll
    for (int e = 0; e < ED; e++) {
        a1[e] = __ldg(&g_attsum[xy[e].x]);
        a2[e] = __ldg(&g_attsum[xy[e].y]);
        int gdst = half ? xy[e].x : xy[e].y;
        h[e] = __ldg(&((const float4*)g_hv)[(long)gdst * 16 + q]);
    }
    float vs = 0.f, vq = 0.f;
#pragma unroll
    for (int e = 0; e < ED; e++) {
        float an1 = l1[e] - __logf(a1[e]);
        float an2 = l2[e] - __logf(a2[e]);
        float an  = half ? an2 : an1;
        int gsrc  = half ? xy[e].y : xy[e].x;
        red_v4(&g_msg[(long)gsrc * NOUT + q * 4],
               make_float4(h[e].x * an, h[e].y * an, h[e].z * an, h[e].w * an));
        if (l == 0) { vs += an1 + an2; vq += an1 * an1 + an2 * an2; }
    }
    if (l == 0) { ssum[threadIdx.x >> 5] = vs; ssq[threadIdx.x >> 5] = vq; }
    __syncthreads();
    if (threadIdx.x == 0) {
        float bs = 0.f, bq = 0.f;
#pragma unroll
        for (int i = 0; i < 8; i++) { bs += ssum[i]; bq += ssq[i]; }
        atomicAdd(&g_psum[blockIdx.x & (NPART - 1)], (double)bs);
        atomicAdd(&g_psq [blockIdx.x & (NPART - 1)], (double)bq);
    }
}

// ---------------- k6: agg normalize + out[:,64:128]; block 0 also does variance --
// 16 lanes per node (2 nodes/warp), float4 path.
__global__ void k6_final(float* __restrict__ out, const float* __restrict__ scale) {
    __shared__ double sd[NPART], qd[NPART];
    int lane = threadIdx.x & 31;
    int node = ((blockIdx.x * blockDim.x + threadIdx.x) >> 4);  // 16 lanes/node
    int q = lane & 15;
    float4 m = __ldg(&((const float4*)g_msg)[(long)node * 16 + q]);
    float sq = m.x*m.x + m.y*m.y + m.z*m.z + m.w*m.w;
#pragma unroll
    for (int o = 8; o; o >>= 1) sq += __shfl_xor_sync(FULLM, sq, o);
    float r = __ldg(&g_hn[node]) * __ldg(scale) / fmaxf(sqrtf(sq), EPSV);
    ((float4*)(out + (long)node * 128))[16 + q] =
        make_float4(m.x * r, m.y * r, m.z * r, m.w * r);

    if (blockIdx.x == 0) {
        int t = threadIdx.x;
        sd[t] = g_psum[t]; qd[t] = g_psq[t];
        __syncthreads();
        for (int o = NPART / 2; o; o >>= 1) {
            if (t < o) { sd[t] += sd[t + o]; qd[t] += qd[t + o]; }
            __syncthreads();
        }
        if (t == 0) {
            double E = (double)ND;
            double var = (qd[0] - sd[0] * sd[0] / E) / (E - 1.0);
            out[(long)NN * 128] = (float)var;
        }
    }
}

// ---------------- launch --------------------------------------------------------------
extern "C" void kernel_launch(void* const* d_in, const int* in_sizes, int n_in,
                              void* d_out, int out_size) {
    const float* nf    = (const float*)d_in[0];
    const float* ef    = (const float*)d_in[1];
    const int*   edges = (const int*)  d_in[2];
    const float* W     = (const float*)d_in[3];
    const float* b     = (const float*)d_in[4];
    const float* an    = (const float*)d_in[5];
    const float* scale = (const float*)d_in[6];
    float* out = (float*)d_out;

    const int k1_smem = (8192 + 16384) * 4;  // 96 KB
    cudaFuncSetAttribute(k1_gemm, cudaFuncAttributeMaxDynamicSharedMemorySize, k1_smem);

    k1_gemm   <<<(NN + 127)/128, 256, k1_smem>>>(nf, W, b, an, out);
    kE_edge   <<<NE/16/8, 256>>>(ef, an, edges);     // 3125 blocks, warp = 16 edges
    k4_scatter<<<NE/(8*ED), 256>>>(edges);           // 6250 blocks, warp = 8 edges
    k6_final  <<<NN/16, 256>>>(out, scale);          // 3125 blocks, 16 nodes/block
}